// round 2
// baseline (speedup 1.0000x reference)
#include <cuda_runtime.h>
#include <math.h>

#define NN 50000
#define NE 800000
#define L  64
#define NB32 ((NN + 31) / 32)

// ------------- device scratch (no allocs allowed) -------------
__device__ float  g_H [NN*L];
__device__ float  g_H0[NN*L];
__device__ float  g_Pt[NN*L];
__device__ float  g_Qt[NN*L];
__device__ float  g_Pf[NN*L];
__device__ float  g_Qf[NN*L];
__device__ float  g_mt[NN*L];
__device__ float  g_mf[NN*L];
__device__ float  g_U [NN];
__device__ int    g_rowptr[NN+1];
__device__ int    g_colptr[NN+1];
__device__ int    g_cntr[NN];
__device__ int    g_cntc[NN];
__device__ float4 g_rowE4[NE];
__device__ float4 g_colE4[NE];
__device__ float  g_rowA[NE];
__device__ double g_loss;

__device__ __forceinline__ float sigf(float v){ return 1.f/(1.f+__expf(-v)); }

// ---------------- CSR build ----------------
__global__ void k_init(){
    int i = blockIdx.x*blockDim.x + threadIdx.x;
    if(i < NN){ g_cntr[i]=0; g_cntc[i]=0; }
    if(i == 0) g_loss = 0.0;
}

__global__ void k_hist(const int* __restrict__ ei){
    int e = blockIdx.x*blockDim.x + threadIdx.x;
    if(e < NE){
        atomicAdd(&g_cntr[ei[e]], 1);
        atomicAdd(&g_cntc[ei[NE+e]], 1);
    }
}

__device__ void scan_one(int* cnt, int* ptr, int* part){
    const int C = (NN + 1023)/1024;
    int t = threadIdx.x;
    int s = 0;
    for(int k=0;k<C;k++){ int id=t*C+k; if(id<NN) s += cnt[id]; }
    part[t] = s; __syncthreads();
    for(int off=1; off<1024; off<<=1){
        int v = (t>=off)? part[t-off] : 0;
        __syncthreads();
        part[t] += v;
        __syncthreads();
    }
    int run = (t==0)? 0 : part[t-1];
    for(int k=0;k<C;k++){
        int id = t*C+k;
        if(id<NN){ int v=cnt[id]; ptr[id]=run; run+=v; cnt[id]=0; }
    }
    if(t==0) ptr[NN] = part[1023];
    __syncthreads();
}

__global__ void k_scan(){
    __shared__ int part[1024];
    scan_one(g_cntr, g_rowptr, part);
    scan_one(g_cntc, g_colptr, part);
}

__global__ void k_scatter(const int* __restrict__ ei, const float* __restrict__ ea,
                          const float* __restrict__ aij){
    int e = blockIdx.x*blockDim.x + threadIdx.x;
    if(e >= NE) return;
    int r = ei[e], c = ei[NE+e];
    float a0 = ea[3*e], a1 = ea[3*e+1], a2 = ea[3*e+2];
    int pr = atomicAdd(&g_cntr[r], 1);
    int p  = g_rowptr[r] + pr;
    g_rowE4[p] = make_float4(a0,a1,a2,__int_as_float(c));
    g_rowA[p]  = aij[e];
    int pc = atomicAdd(&g_cntc[c], 1);
    int q  = g_colptr[c] + pc;
    g_colE4[q] = make_float4(a0,a1,a2,__int_as_float(r));
}

// ---------------- encoder: x -> H0, H ----------------
__global__ __launch_bounds__(256) void k_enc0(const float* __restrict__ x,
        const float* __restrict__ eW1, const float* __restrict__ eb1,
        const float* __restrict__ eW2, const float* __restrict__ eb2){
    __shared__ float sW[L*L];
    __shared__ float sh[8][4][L];
    int tid = threadIdx.x;
    for(int i=tid;i<L*L;i+=256) sW[i]=eW2[i];
    __syncthreads();
    int lane = tid&31, w = tid>>5, c0 = 2*lane;
    int nb = blockIdx.x*32 + w*4;
    float w1a=eW1[c0], w1b=eW1[c0+1], b1a=eb1[c0], b1b=eb1[c0+1];
    float b2a=eb2[c0], b2b=eb2[c0+1];
    bool val[4];
    #pragma unroll
    for(int v=0;v<4;v++){
        int n = nb+v; val[v] = (n<NN);
        float xv = val[v]? x[n] : 0.f;
        sh[w][v][c0]   = fmaxf(fmaf(xv,w1a,b1a),0.f);
        sh[w][v][c0+1] = fmaxf(fmaf(xv,w1b,b1b),0.f);
    }
    __syncwarp();
    float a0[4]={b2a,b2a,b2a,b2a}, a1[4]={b2b,b2b,b2b,b2b};
    for(int k=0;k<L;k++){
        float2 wv = *(const float2*)&sW[k*L+c0];
        #pragma unroll
        for(int v=0;v<4;v++){ float s=sh[w][v][k]; a0[v]=fmaf(s,wv.x,a0[v]); a1[v]=fmaf(s,wv.y,a1[v]); }
    }
    #pragma unroll
    for(int v=0;v<4;v++) if(val[v]){
        int n = nb+v;
        g_H0[n*L+c0]=a0[v]; g_H0[n*L+c0+1]=a1[v];
        g_H [n*L+c0]=a0[v]; g_H [n*L+c0+1]=a1[v];
    }
}

// ---------------- P/Q precompute (both phis) ----------------
#define PREP_SMEM ((4*L*L + 32*L)*4)
__global__ __launch_bounds__(256) void k_prep(
        const float* __restrict__ ptW1, const float* __restrict__ ptb1,
        const float* __restrict__ pfW1, const float* __restrict__ pfb1){
    extern __shared__ float sm[];
    float* Wat = sm;            // ptW1 rows 0..63
    float* Wbt = sm + L*L;      // ptW1 rows 64..127
    float* Waf = sm + 2*L*L;
    float* Wbf = sm + 3*L*L;
    float* stg = sm + 4*L*L;    // [32][64] H rows
    int tid = threadIdx.x;
    for(int i=tid;i<L*L;i+=256){
        Wat[i]=ptW1[i]; Wbt[i]=ptW1[L*L+i];
        Waf[i]=pfW1[i]; Wbf[i]=pfW1[L*L+i];
    }
    int lane = tid&31, w = tid>>5, c0 = 2*lane;
    int nb = blockIdx.x*32 + w*4;
    bool val[4];
    #pragma unroll
    for(int v=0;v<4;v++){
        int n = nb+v; val[v] = (n<NN);
        float h0 = val[v]? g_H[n*L+c0]   : 0.f;
        float h1 = val[v]? g_H[n*L+c0+1] : 0.f;
        stg[(w*4+v)*L + c0]   = h0;
        stg[(w*4+v)*L + c0+1] = h1;
    }
    __syncthreads();
    float pt0[4],pt1[4],qt0[4],qt1[4],pf0[4],pf1[4],qf0[4],qf1[4];
    float bt0=ptb1[c0], bt1=ptb1[c0+1], bf0=pfb1[c0], bf1=pfb1[c0+1];
    #pragma unroll
    for(int v=0;v<4;v++){ pt0[v]=bt0; pt1[v]=bt1; pf0[v]=bf0; pf1[v]=bf1; qt0[v]=qt1[v]=qf0[v]=qf1[v]=0.f; }
    for(int k=0;k<L;k++){
        float2 wat = *(const float2*)&Wat[k*L+c0];
        float2 wbt = *(const float2*)&Wbt[k*L+c0];
        float2 waf = *(const float2*)&Waf[k*L+c0];
        float2 wbf = *(const float2*)&Wbf[k*L+c0];
        #pragma unroll
        for(int v=0;v<4;v++){
            float h = stg[(w*4+v)*L + k];
            pt0[v]=fmaf(h,wat.x,pt0[v]); pt1[v]=fmaf(h,wat.y,pt1[v]);
            qt0[v]=fmaf(h,wbt.x,qt0[v]); qt1[v]=fmaf(h,wbt.y,qt1[v]);
            pf0[v]=fmaf(h,waf.x,pf0[v]); pf1[v]=fmaf(h,waf.y,pf1[v]);
            qf0[v]=fmaf(h,wbf.x,qf0[v]); qf1[v]=fmaf(h,wbf.y,qf1[v]);
        }
    }
    #pragma unroll
    for(int v=0;v<4;v++) if(val[v]){
        int n = nb+v;
        g_Pt[n*L+c0]=pt0[v]; g_Pt[n*L+c0+1]=pt1[v];
        g_Qt[n*L+c0]=qt0[v]; g_Qt[n*L+c0+1]=qt1[v];
        g_Pf[n*L+c0]=pf0[v]; g_Pf[n*L+c0+1]=pf1[v];
        g_Qf[n*L+c0]=qf0[v]; g_Qf[n*L+c0+1]=qf1[v];
    }
}

// ---------------- edge aggregation + W2 fold: mess = (Σ relu)@W2 + deg*b2 ----------------
__global__ __launch_bounds__(256) void k_aggr(
        const int* __restrict__ ptr, const float4* __restrict__ e4,
        const float* __restrict__ P, const float* __restrict__ Q,
        const float* __restrict__ W1full, const float* __restrict__ b2,
        const float* __restrict__ W2, float* __restrict__ out){
    __shared__ float sW2[L*L];
    __shared__ float sWe[3*L];
    __shared__ float sS[8][4][L];
    int tid = threadIdx.x;
    for(int i=tid;i<L*L;i+=256) sW2[i]=W2[i];
    for(int i=tid;i<3*L;i+=256) sWe[i]=W1full[2*L*L + i]; // rows 128..130
    __syncthreads();
    int lane = tid&31, w = tid>>5, c0 = 2*lane;
    int nb = blockIdx.x*32 + w*4;
    float we0a=sWe[c0],     we0b=sWe[c0+1];
    float we1a=sWe[L+c0],   we1b=sWe[L+c0+1];
    float we2a=sWe[2*L+c0], we2b=sWe[2*L+c0+1];
    float degv[4]; bool val[4];
    #pragma unroll
    for(int v=0;v<4;v++){
        int n = nb+v; val[v] = (n<NN);
        float acc0=0.f, acc1=0.f; int cnt=0;
        if(val[v]){
            float base0 = P[n*L+c0], base1 = P[n*L+c0+1];
            int s = ptr[n], e = ptr[n+1];
            for(int p=s; p<e; p++){
                float4 E = e4[p];
                int j = __float_as_int(E.w);
                if(j == n) continue;
                cnt++;
                float2 q = *(const float2*)&Q[j*L+c0];
                float pre0 = base0 + q.x + E.x*we0a + E.y*we1a + E.z*we2a;
                float pre1 = base1 + q.y + E.x*we0b + E.y*we1b + E.z*we2b;
                acc0 += fmaxf(pre0, 0.f);
                acc1 += fmaxf(pre1, 0.f);
            }
        }
        sS[w][v][c0]=acc0; sS[w][v][c0+1]=acc1; degv[v]=(float)cnt;
    }
    __syncwarp();
    float b2a=b2[c0], b2b=b2[c0+1];
    float o0[4],o1[4];
    #pragma unroll
    for(int v=0;v<4;v++){ o0[v]=degv[v]*b2a; o1[v]=degv[v]*b2b; }
    for(int k=0;k<L;k++){
        float2 wv = *(const float2*)&sW2[k*L+c0];
        #pragma unroll
        for(int v=0;v<4;v++){ float s=sS[w][v][k]; o0[v]=fmaf(s,wv.x,o0[v]); o1[v]=fmaf(s,wv.y,o1[v]); }
    }
    #pragma unroll
    for(int v=0;v<4;v++) if(val[v]){
        int n = nb+v;
        out[n*L+c0]=o0[v]; out[n*L+c0+1]=o1[v];
    }
}

// ---------------- fused node update + decoder + aux losses ----------------
#define NODE_SMEM ((3*194*L + 2*L*L + 32*196 + 32*L)*4)
__global__ __launch_bounds__(256) void k_node(
        const int* __restrict__ tags, const float* __restrict__ prb,
        const float* __restrict__ zkW, const float* __restrict__ zkb,
        const float* __restrict__ rkW, const float* __restrict__ rkb,
        const float* __restrict__ cW,  const float* __restrict__ cb,
        const float* __restrict__ dW1, const float* __restrict__ db1,
        const float* __restrict__ dW2, const float* __restrict__ db2,
        const float* __restrict__ eW1, const float* __restrict__ eb1,
        const float* __restrict__ eW2, const float* __restrict__ eb2){
    extern __shared__ float sm[];
    float* szk  = sm;                 // 194*64
    float* srk  = szk + 194*L;
    float* scw  = srk + 194*L;
    float* sdW1 = scw + 194*L;        // 64*64
    float* seW2 = sdW1 + L*L;         // 64*64
    float* stgA = seW2 + L*L;         // [32][196]
    float* stgB = stgA + 32*196;      // [32][64]
    __shared__ float sdW2[L], sdb1[L], sE1[L], sEb1[L], szb[L], srb[L], scb[L], sEb2[L];
    __shared__ double red[8];
    int tid = threadIdx.x;
    for(int i=tid;i<194*L;i+=256){ szk[i]=zkW[i]; srk[i]=rkW[i]; scw[i]=cW[i]; }
    for(int i=tid;i<L*L;i+=256){ sdW1[i]=dW1[i]; seW2[i]=eW2[i]; }
    if(tid<L){ sdW2[tid]=dW2[tid]; sdb1[tid]=db1[tid]; sE1[tid]=eW1[tid]; sEb1[tid]=eb1[tid];
               szb[tid]=zkb[tid]; srb[tid]=rkb[tid]; scb[tid]=cb[tid]; sEb2[tid]=eb2[tid]; }
    __syncthreads();
    int lane = tid&31, w = tid>>5, c0 = 2*lane;
    int nb = blockIdx.x*32 + w*4;
    float db2v = db2[0];
    bool val[4];
    // stage cat = [H, mt, mf, prb]
    #pragma unroll
    for(int v=0;v<4;v++){
        int n = nb+v; val[v] = (n<NN);
        float* A = stgA + (w*4+v)*196;
        if(val[v]){
            A[c0]       = g_H [n*L+c0];  A[c0+1]     = g_H [n*L+c0+1];
            A[64+c0]    = g_mt[n*L+c0];  A[64+c0+1]  = g_mt[n*L+c0+1];
            A[128+c0]   = g_mf[n*L+c0];  A[128+c0+1] = g_mf[n*L+c0+1];
            if(lane==0){ A[192]=prb[2*n]; A[193]=prb[2*n+1]; }
        } else {
            A[c0]=A[c0+1]=A[64+c0]=A[64+c0+1]=A[128+c0]=A[128+c0+1]=0.f;
            if(lane==0){ A[192]=0.f; A[193]=0.f; }
        }
    }
    __syncwarp();
    float az0[4],az1[4],ar0[4],ar1[4],ac0[4],ac1[4];
    #pragma unroll
    for(int v=0;v<4;v++){ az0[v]=az1[v]=ar0[v]=ar1[v]=ac0[v]=ac1[v]=0.f; }
    for(int k=0;k<64;k++){
        float2 wz = *(const float2*)&szk[k*L+c0];
        float2 wr = *(const float2*)&srk[k*L+c0];
        #pragma unroll
        for(int v=0;v<4;v++){
            float cv = stgA[(w*4+v)*196 + k];
            az0[v]=fmaf(cv,wz.x,az0[v]); az1[v]=fmaf(cv,wz.y,az1[v]);
            ar0[v]=fmaf(cv,wr.x,ar0[v]); ar1[v]=fmaf(cv,wr.y,ar1[v]);
        }
    }
    for(int k=64;k<194;k++){
        float2 wz = *(const float2*)&szk[k*L+c0];
        float2 wr = *(const float2*)&srk[k*L+c0];
        float2 wc = *(const float2*)&scw[k*L+c0];
        #pragma unroll
        for(int v=0;v<4;v++){
            float cv = stgA[(w*4+v)*196 + k];
            az0[v]=fmaf(cv,wz.x,az0[v]); az1[v]=fmaf(cv,wz.y,az1[v]);
            ar0[v]=fmaf(cv,wr.x,ar0[v]); ar1[v]=fmaf(cv,wr.y,ar1[v]);
            ac0[v]=fmaf(cv,wc.x,ac0[v]); ac1[v]=fmaf(cv,wc.y,ac1[v]);
        }
    }
    float z0[4],z1[4];
    #pragma unroll
    for(int v=0;v<4;v++){
        z0[v]=sigf(az0[v]+szb[c0]); z1[v]=sigf(az1[v]+szb[c0+1]);
        float r0=sigf(ar0[v]+srb[c0]), r1=sigf(ar1[v]+srb[c0+1]);
        stgB[(w*4+v)*L+c0]=r0; stgB[(w*4+v)*L+c0+1]=r1;
    }
    __syncwarp();
    for(int k=0;k<64;k++){
        float2 wc = *(const float2*)&scw[k*L+c0];
        #pragma unroll
        for(int v=0;v<4;v++){
            float rh = stgB[(w*4+v)*L+k] * stgA[(w*4+v)*196+k];
            ac0[v]=fmaf(rh,wc.x,ac0[v]); ac1[v]=fmaf(rh,wc.y,ac1[v]);
        }
    }
    // Hn, write back, restage
    float Hn0[4], Hn1[4];
    #pragma unroll
    for(int v=0;v<4;v++){
        int n = nb+v;
        float* A = stgA + (w*4+v)*196;
        float co0 = tanhf(ac0[v]+scb[c0]);
        float co1 = tanhf(ac1[v]+scb[c0+1]);
        float h0 = A[c0], h1 = A[c0+1];
        float hn0 = h0 + z0[v]*co0, hn1 = h1 + z1[v]*co1;
        if(val[v] && tags[n]==1){ hn0 = g_H0[n*L+c0]; hn1 = g_H0[n*L+c0+1]; }
        Hn0[v]=hn0; Hn1[v]=hn1;
        A[c0]=hn0; A[c0+1]=hn1;
        if(val[v]){ g_H[n*L+c0]=hn0; g_H[n*L+c0+1]=hn1; }
    }
    __syncwarp();
    // decoder: U = relu(Hn@dW1+db1)@dW2 + db2
    float ad0[4],ad1[4];
    #pragma unroll
    for(int v=0;v<4;v++){ ad0[v]=sdb1[c0]; ad1[v]=sdb1[c0+1]; }
    for(int k=0;k<L;k++){
        float2 wd = *(const float2*)&sdW1[k*L+c0];
        #pragma unroll
        for(int v=0;v<4;v++){
            float hk = stgA[(w*4+v)*196 + k];
            ad0[v]=fmaf(hk,wd.x,ad0[v]); ad1[v]=fmaf(hk,wd.y,ad1[v]);
        }
    }
    float Uv[4];
    #pragma unroll
    for(int v=0;v<4;v++){
        float pu = fmaxf(ad0[v],0.f)*sdW2[c0] + fmaxf(ad1[v],0.f)*sdW2[c0+1];
        for(int o=16;o;o>>=1) pu += __shfl_xor_sync(0xffffffffu, pu, o);
        Uv[v] = pu + db2v;
        int n = nb+v;
        if(val[v] && lane==0) g_U[n] = Uv[v];
        // enc hidden of U
        float eh0 = fmaxf(fmaf(Uv[v],sE1[c0],sEb1[c0]),0.f);
        float eh1 = fmaxf(fmaf(Uv[v],sE1[c0+1],sEb1[c0+1]),0.f);
        stgB[(w*4+v)*L+c0]=eh0; stgB[(w*4+v)*L+c0+1]=eh1;
    }
    __syncwarp();
    // enc(U): 64x64 GEMV
    float ae0[4],ae1[4];
    #pragma unroll
    for(int v=0;v<4;v++){ ae0[v]=sEb2[c0]; ae1[v]=sEb2[c0+1]; }
    for(int k=0;k<L;k++){
        float2 we = *(const float2*)&seW2[k*L+c0];
        #pragma unroll
        for(int v=0;v<4;v++){
            float ek = stgB[(w*4+v)*L+k];
            ae0[v]=fmaf(ek,we.x,ae0[v]); ae1[v]=fmaf(ek,we.y,ae1[v]);
        }
    }
    float encS = 0.f;
    #pragma unroll
    for(int v=0;v<4;v++){
        float* A = stgA + (w*4+v)*196;
        if(val[v]){
            float d0 = ae0[v]-Hn0[v], d1 = ae1[v]-Hn1[v];
            encS += d0*d0 + d1*d1;
        }
        A[64+c0]=ae0[v]; A[64+c0+1]=ae1[v];   // stash enc for autoenc pass
    }
    __syncwarp();
    // autoenc: dec(enc)
    float ag0[4],ag1[4];
    #pragma unroll
    for(int v=0;v<4;v++){ ag0[v]=sdb1[c0]; ag1[v]=sdb1[c0+1]; }
    for(int k=0;k<L;k++){
        float2 wd = *(const float2*)&sdW1[k*L+c0];
        #pragma unroll
        for(int v=0;v<4;v++){
            float ek = stgA[(w*4+v)*196 + 64 + k];
            ag0[v]=fmaf(ek,wd.x,ag0[v]); ag1[v]=fmaf(ek,wd.y,ag1[v]);
        }
    }
    float autoS = 0.f;
    #pragma unroll
    for(int v=0;v<4;v++){
        float pa = fmaxf(ag0[v],0.f)*sdW2[c0] + fmaxf(ag1[v],0.f)*sdW2[c0+1];
        for(int o=16;o;o>>=1) pa += __shfl_xor_sync(0xffffffffu, pa, o);
        float aout = pa + db2v;
        if(val[v] && lane==0){ float d = aout - Uv[v]; autoS += d*d; }
    }
    // loss reduction: enc_loss/(N*64) + autoenc_loss/N
    float tot = encS;
    for(int o=16;o;o>>=1) tot += __shfl_xor_sync(0xffffffffu, tot, o);
    float at = autoS;
    for(int o=16;o;o>>=1) at += __shfl_xor_sync(0xffffffffu, at, o);
    if(lane==0) red[w] = (double)tot/((double)NN*64.0) + (double)at/(double)NN;
    __syncthreads();
    if(tid==0){
        double s = 0.0;
        for(int i=0;i<8;i++) s += red[i];
        atomicAdd(&g_loss, s);
    }
}

// ---------------- residual loss ----------------
__global__ __launch_bounds__(256) void k_res(const float* __restrict__ y, float wgt){
    __shared__ double red[8];
    int lane = threadIdx.x&31, w = threadIdx.x>>5;
    int wid = blockIdx.x*8 + w;
    int nwarps = gridDim.x*8;
    float ls = 0.f;
    for(int n = wid; n < NN; n += nwarps){
        int s = g_rowptr[n], e = g_rowptr[n+1];
        float part = 0.f;
        for(int p = s+lane; p < e; p += 32){
            int j = __float_as_int(g_rowE4[p].w);
            part += g_rowA[p] * g_U[j];
        }
        for(int o=16;o;o>>=1) part += __shfl_xor_sync(0xffffffffu, part, o);
        if(lane==0){ float d = part - y[n]; ls += d*d; }
    }
    for(int o=16;o;o>>=1) ls += __shfl_xor_sync(0xffffffffu, ls, o);
    if(lane==0) red[w] = (double)ls;
    __syncthreads();
    if(threadIdx.x==0){
        double s=0.0; for(int i=0;i<8;i++) s+=red[i];
        atomicAdd(&g_loss, s * (double)wgt / (double)NN);
    }
}

// ---------------- finalize ----------------
__global__ void k_fin(float* __restrict__ out, int out_size){
    int i = blockIdx.x*blockDim.x + threadIdx.x;
    if(i < NN && i < out_size) out[i] = g_U[i];
    if(i == NN && i < out_size) out[NN] = (float)g_loss;
}

extern "C" void kernel_launch(void* const* d_in, const int* in_sizes, int n_in,
                              void* d_out, int out_size){
    const float* x    = (const float*)d_in[0];
    // d_in[1] = sol (unused)
    const float* y    = (const float*)d_in[2];
    const int*   tags = (const int*)  d_in[3];
    const int*   ei   = (const int*)  d_in[4];
    const float* ea   = (const float*)d_in[5];
    const float* aij  = (const float*)d_in[6];
    const float* prb  = (const float*)d_in[7];
    const float* ptW1 = (const float*)d_in[8];
    const float* ptb1 = (const float*)d_in[9];
    const float* ptW2 = (const float*)d_in[10];
    const float* ptb2 = (const float*)d_in[11];
    const float* pfW1 = (const float*)d_in[12];
    const float* pfb1 = (const float*)d_in[13];
    const float* pfW2 = (const float*)d_in[14];
    const float* pfb2 = (const float*)d_in[15];
    const float* zkW  = (const float*)d_in[16];
    const float* zkb  = (const float*)d_in[17];
    const float* rkW  = (const float*)d_in[18];
    const float* rkb  = (const float*)d_in[19];
    const float* cW   = (const float*)d_in[20];
    const float* cb   = (const float*)d_in[21];
    const float* eW1  = (const float*)d_in[22];
    const float* eb1  = (const float*)d_in[23];
    const float* eW2  = (const float*)d_in[24];
    const float* eb2  = (const float*)d_in[25];
    const float* dW1  = (const float*)d_in[26];
    const float* db1  = (const float*)d_in[27];
    const float* dW2  = (const float*)d_in[28];
    const float* db2  = (const float*)d_in[29];

    cudaFuncSetAttribute(k_prep, cudaFuncAttributeMaxDynamicSharedMemorySize, PREP_SMEM);
    cudaFuncSetAttribute(k_node, cudaFuncAttributeMaxDynamicSharedMemorySize, NODE_SMEM);

    float4* rowE4; cudaGetSymbolAddress((void**)&rowE4, g_rowE4);
    float4* colE4; cudaGetSymbolAddress((void**)&colE4, g_colE4);
    int* rowptr;   cudaGetSymbolAddress((void**)&rowptr, g_rowptr);
    int* colptr;   cudaGetSymbolAddress((void**)&colptr, g_colptr);
    float* Pt; cudaGetSymbolAddress((void**)&Pt, g_Pt);
    float* Qt; cudaGetSymbolAddress((void**)&Qt, g_Qt);
    float* Pf; cudaGetSymbolAddress((void**)&Pf, g_Pf);
    float* Qf; cudaGetSymbolAddress((void**)&Qf, g_Qf);
    float* mt; cudaGetSymbolAddress((void**)&mt, g_mt);
    float* mf; cudaGetSymbolAddress((void**)&mf, g_mf);

    k_init<<<(NN+255)/256, 256>>>();
    k_hist<<<(NE+255)/256, 256>>>(ei);
    k_scan<<<1, 1024>>>();
    k_scatter<<<(NE+255)/256, 256>>>(ei, ea, aij);
    k_enc0<<<NB32, 256>>>(x, eW1, eb1, eW2, eb2);

    const float gammaw[2] = {0.9f, 1.0f};
    for(int step=0; step<2; step++){
        k_prep<<<NB32, 256, PREP_SMEM>>>(ptW1, ptb1, pfW1, pfb1);
        // mess_to: i = col (col-CSR), neighbor j = row
        k_aggr<<<NB32, 256>>>(colptr, colE4, Pt, Qt, ptW1, ptb2, ptW2, mt);
        // mess_from: i = row (row-CSR), neighbor j = col
        k_aggr<<<NB32, 256>>>(rowptr, rowE4, Pf, Qf, pfW1, pfb2, pfW2, mf);
        k_node<<<NB32, 256, NODE_SMEM>>>(tags, prb, zkW, zkb, rkW, rkb, cW, cb,
                                         dW1, db1, dW2, db2, eW1, eb1, eW2, eb2);
        k_res<<<NB32, 256>>>(y, gammaw[step]);
    }
    k_fin<<<(NN+256)/256, 256>>>((float*)d_out, out_size);
}